// round 9
// baseline (speedup 1.0000x reference)
#include <cuda_runtime.h>
#include <cuda_bf16.h>
#include <math.h>
#include <cstdint>

// Shapes (fixed)
//   x: (4,256,64,64) f32 | conv_offset_w: (27,256,3,3) | conv_offset_b: (27,)
//   dcn_weight: (256,256,3,3) | out: (4,256,64,64) f32
//
// Pipeline (all tensor-core):
//   K2a permute dcn_weight    -> g_wB[o][k']      tf32, k 8-group permuted
//   K2b permute conv_offset_w -> g_wOffHi/Lo[32][k'] split-tf32
//   K3  offset implicit GEMM  -> g_om  (split-tf32, reg-prefetched gather)
//   K4  FUSED sample+GEMM, WARP-SPECIALIZED: 2 producer warps gather A into a
//       3-stage ring (mbarrier handoff), 8 consumer warps run tf32 mma.sync.

#define NN 4
#define CC 256
#define HH 64
#define WW 64
#define OC 256
#define KDIM 2304
#define MDIM 16384
#define NTILES 72

__device__ __align__(128) float g_om[NN * 27 * HH * WW];
__device__ __align__(128) float g_wB[OC * KDIM];
__device__ __align__(128) float g_wOffHi[32 * KDIM];
__device__ __align__(128) float g_wOffLo[32 * KDIM];

__device__ __forceinline__ float to_tf32(float v) {
    uint32_t u;
    asm("cvt.rna.tf32.f32 %0, %1;" : "=r"(u) : "f"(v));
    return __uint_as_float(u);
}
__device__ __forceinline__ uint32_t smem_u32(const void* p) {
    uint32_t a;
    asm("{ .reg .u64 t; cvta.to.shared.u64 t, %1; cvt.u32.u64 %0, t; }"
        : "=r"(a) : "l"(p));
    return a;
}
__device__ __forceinline__ void cp_async16(uint32_t d, const void* s) {
    asm volatile("cp.async.cg.shared.global [%0], [%1], 16;"
                 :: "r"(d), "l"(s) : "memory");
}

#define MMA_TF32(c_, a_, b_)                                                  \
    asm volatile(                                                             \
        "mma.sync.aligned.m16n8k8.row.col.f32.tf32.tf32.f32 "                 \
        "{%0,%1,%2,%3}, {%4,%5,%6,%7}, {%8,%9}, {%0,%1,%2,%3};"               \
        : "+f"((c_)[0]), "+f"((c_)[1]), "+f"((c_)[2]), "+f"((c_)[3])          \
        : "r"((a_)[0]), "r"((a_)[1]), "r"((a_)[2]), "r"((a_)[3]),             \
          "r"((b_)[0]), "r"((b_)[1]))

#define MBAR_INIT(a_, c_) \
    asm volatile("mbarrier.init.shared.b64 [%0], %1;" :: "r"(a_), "r"(c_) : "memory")
#define MBAR_ARRIVE(a_) \
    asm volatile("mbarrier.arrive.shared.b64 _, [%0];" :: "r"(a_) : "memory")
#define MBAR_WAIT(a_, ph_) do {                                               \
    asm volatile(                                                             \
        "{ .reg .pred P;\n\t"                                                 \
        "W_%=:\n\t"                                                           \
        "mbarrier.try_wait.parity.acquire.cta.shared::cta.b64 P, [%0], %1, 0x989680;\n\t" \
        "@P bra.uni D_%=;\n\t"                                                \
        "bra.uni W_%=;\n\t"                                                   \
        "D_%=: }"                                                             \
        :: "r"(a_), "r"(ph_) : "memory");                                     \
} while (0)

// ---------------------------------------------------------------------------
// K2a: permute dcn_weight (o,c,kk) -> g_wB[o][k'], tf32-rounded, k-permuted
// ---------------------------------------------------------------------------
__global__ __launch_bounds__(256) void permute_w_kernel(const float* __restrict__ dw)
{
    int o = blockIdx.x;
    int c = threadIdx.x;
    int cp = (c & 0xF8) | ((c & 3) << 1) | ((c >> 2) & 1);
    const float* src = dw + (size_t)(o * CC + c) * 9;
    float* dst = g_wB + (size_t)o * KDIM + cp;
#pragma unroll
    for (int kk = 0; kk < 9; kk++)
        dst[kk * 256] = to_tf32(src[kk]);
}

// ---------------------------------------------------------------------------
// K2b: permute conv_offset_w -> g_wOffHi/Lo[32][k'] (split-tf32)
// ---------------------------------------------------------------------------
__global__ __launch_bounds__(256) void permute_woff_kernel(const float* __restrict__ wo)
{
    int o = blockIdx.x;
    int c = threadIdx.x;
    int cp = (c & 0xF8) | ((c & 3) << 1) | ((c >> 2) & 1);
    float* dh = g_wOffHi + (size_t)o * KDIM + cp;
    float* dl = g_wOffLo + (size_t)o * KDIM + cp;
    if (o < 27) {
        const float* src = wo + (size_t)(o * CC + c) * 9;
#pragma unroll
        for (int kk = 0; kk < 9; kk++) {
            float v = src[kk];
            float h = to_tf32(v);
            dh[kk * 256] = h;
            dl[kk * 256] = to_tf32(v - h);
        }
    } else {
#pragma unroll
        for (int kk = 0; kk < 9; kk++) { dh[kk * 256] = 0.f; dl[kk * 256] = 0.f; }
    }
}

// ---------------------------------------------------------------------------
// K3: offset conv as split-tf32 implicit GEMM, register-prefetched gather.
// BM=128, BN=32, BK=32.  smem: A 2buf x 32KB @0 | B 4 stages x 8KB @65536
// ---------------------------------------------------------------------------
#define OSM_A 0
#define OSM_B 65536
#define OFF_SMEM 98304

__global__ __launch_bounds__(256, 1) void offset_gemm_kernel(
    const float* __restrict__ x, const float* __restrict__ bias)
{
    extern __shared__ __align__(128) char smem[];
    const uint32_t sbase = smem_u32(smem);
    const int tid = threadIdx.x;
    const int m0 = blockIdx.x * 128;
    const int nimg = m0 >> 12;
    const int y0 = (m0 & 4095) >> 6;

    const int ldrow = tid >> 3;
    const int ldcol = tid & 7;
    const int swzb  = ldcol ^ (ldrow & 7);
    const char* gBh = (const char*)(g_wOffHi + (size_t)ldrow * KDIM) + ldcol * 16;
    const char* gBl = (const char*)(g_wOffLo + (size_t)ldrow * KDIM) + ldcol * 16;
    const uint32_t dBh = sbase + OSM_B + ldrow * 128 + swzb * 16;

#define LOAD_OB(tt_) do {                                                     \
    uint32_t so_ = ((tt_) & 3) * 8192;                                        \
    size_t   ko_ = (size_t)(tt_) * 128;                                       \
    cp_async16(dBh + so_, gBh + ko_);                                         \
    cp_async16(dBh + so_ + 4096, gBl + ko_);                                  \
} while (0)

    LOAD_OB(0); asm volatile("cp.async.commit_group;" ::: "memory");
    LOAD_OB(1); asm volatile("cp.async.commit_group;" ::: "memory");
    LOAD_OB(2); asm volatile("cp.async.commit_group;" ::: "memory");

    const int mloc = tid & 127;
    const int half = tid >> 7;
    const int lane = tid & 31, warp = tid >> 5;
    const int g  = lane >> 2, tg = lane & 3;
    const int wm = warp * 16;

    const float* xn = x + (size_t)nimg * CC * 4096;

    float c[4][4];
#pragma unroll
    for (int i = 0; i < 4; i++)
#pragma unroll
        for (int r = 0; r < 4; r++) c[i][r] = 0.f;

    int soff = 0;
    bool valid = false;
    float R0[16], R1[16];

    auto gather16 = [&](float* R, int tt) {
        if ((tt & 7) == 0) {
            int kk = tt >> 3;
            int yy = y0 + (mloc >> 6) + kk / 3 - 1;
            int xx = (mloc & 63) + kk % 3 - 1;
            valid = ((unsigned)yy < 64u) && ((unsigned)xx < 64u);
            soff = yy * 64 + xx;
        }
        const float* xp = xn + (size_t)((tt & 7) * 32) * 4096;
#pragma unroll
        for (int i = 0; i < 8; i++) {
            int ct = half * 16 + (i >> 2) * 8 + (i & 3);
            R[i * 2]     = valid ? __ldg(xp + (size_t)ct * 4096 + soff) : 0.f;
            R[i * 2 + 1] = valid ? __ldg(xp + (size_t)(ct + 4) * 4096 + soff) : 0.f;
        }
    };
    auto sts16 = [&](const float* R, int tt) {
        const uint32_t Awh = sbase + OSM_A + (tt & 1) * 32768 + mloc * 128;
#pragma unroll
        for (int i = 0; i < 8; i++) {
            int q = i & 3;
            int ct = half * 16 + (i >> 2) * 8 + q;
            float v0 = R[i * 2], v1 = R[i * 2 + 1];
            float h0 = to_tf32(v0), l0 = to_tf32(v0 - h0);
            float h1 = to_tf32(v1), l1 = to_tf32(v1 - h1);
            int cp = (ct & 0x18) | (q << 1);
            uint32_t off = ((((uint32_t)cp >> 2) ^ (mloc & 7)) << 4) + ((cp & 3) << 2);
            asm volatile("st.shared.v2.b32 [%0], {%1,%2};"
                         :: "r"(Awh + off),
                            "r"(__float_as_uint(h0)), "r"(__float_as_uint(h1)) : "memory");
            asm volatile("st.shared.v2.b32 [%0], {%1,%2};"
                         :: "r"(Awh + 16384 + off),
                            "r"(__float_as_uint(l0)), "r"(__float_as_uint(l1)) : "memory");
        }
    };
    auto mma_tile = [&](int tt) {
        const uint32_t As = sbase + OSM_A + (tt & 1) * 32768;
        const uint32_t Bs = sbase + OSM_B + (tt & 3) * 8192;
#pragma unroll
        for (int ks = 0; ks < 4; ks++) {
            const int ch = ks * 2 + (tg >> 1);
            const int hb = (tg & 1) << 3;
            uint32_t ah[4], al[4];
            {
                int r1 = wm + g, r2 = r1 + 8;
                uint32_t ad1 = As + r1 * 128 + ((ch ^ (r1 & 7)) << 4) + hb;
                uint32_t ad2 = As + r2 * 128 + ((ch ^ (r2 & 7)) << 4) + hb;
                asm volatile("ld.shared.v2.b32 {%0,%1}, [%2];"
                             : "=r"(ah[0]), "=r"(ah[2]) : "r"(ad1));
                asm volatile("ld.shared.v2.b32 {%0,%1}, [%2];"
                             : "=r"(ah[1]), "=r"(ah[3]) : "r"(ad2));
                asm volatile("ld.shared.v2.b32 {%0,%1}, [%2];"
                             : "=r"(al[0]), "=r"(al[2]) : "r"(ad1 + 16384));
                asm volatile("ld.shared.v2.b32 {%0,%1}, [%2];"
                             : "=r"(al[1]), "=r"(al[3]) : "r"(ad2 + 16384));
            }
#pragma unroll
            for (int nt = 0; nt < 4; nt++) {
                int rr = nt * 8 + g;
                uint32_t bd = Bs + rr * 128 + ((ch ^ (rr & 7)) << 4) + hb;
                uint32_t bh[2], bl[2];
                asm volatile("ld.shared.v2.b32 {%0,%1}, [%2];"
                             : "=r"(bh[0]), "=r"(bh[1]) : "r"(bd));
                asm volatile("ld.shared.v2.b32 {%0,%1}, [%2];"
                             : "=r"(bl[0]), "=r"(bl[1]) : "r"(bd + 4096));
                MMA_TF32(c[nt], ah, bh);
                MMA_TF32(c[nt], ah, bl);
                MMA_TF32(c[nt], al, bh);
            }
        }
    };

    gather16(R0, 0);

#pragma unroll 1
    for (int t = 0; t < NTILES; t += 2) {
        sts16(R0, t);
        gather16(R1, t + 1);
        asm volatile("cp.async.wait_group 2;" ::: "memory");
        __syncthreads();
        if (t + 3 < NTILES) LOAD_OB(t + 3);
        asm volatile("cp.async.commit_group;" ::: "memory");
        mma_tile(t);

        sts16(R1, t + 1);
        if (t + 2 < NTILES) gather16(R0, t + 2);
        asm volatile("cp.async.wait_group 2;" ::: "memory");
        __syncthreads();
        if (t + 4 < NTILES) LOAD_OB(t + 4);
        asm volatile("cp.async.commit_group;" ::: "memory");
        mma_tile(t + 1);
    }

    float* ob = g_om + (size_t)nimg * 27 * 4096 + (m0 & 4095);
    int lm = wm + g;
#pragma unroll
    for (int nt = 0; nt < 4; nt++) {
        int oc0 = nt * 8 + tg * 2;
        if (oc0 < 27) {
            float bb = bias[oc0];
            ob[(size_t)oc0 * 4096 + lm]     = c[nt][0] + bb;
            ob[(size_t)oc0 * 4096 + lm + 8] = c[nt][2] + bb;
        }
        if (oc0 + 1 < 27) {
            float bb = bias[oc0 + 1];
            ob[(size_t)(oc0 + 1) * 4096 + lm]     = c[nt][1] + bb;
            ob[(size_t)(oc0 + 1) * 4096 + lm + 8] = c[nt][3] + bb;
        }
    }
}

// ---------------------------------------------------------------------------
// K4: WARP-SPECIALIZED fused sample+GEMM.
// 320 threads: tid<256 consumers (8 warps, MMA), tid>=256 producers (2 warps).
// smem: A ring 3x16KB @0 | B ring 4x32KB @49152 | mbarriers @180224
//   fullA[3] (count 64), emptyA[3] (count 256)
// ---------------------------------------------------------------------------
#define FSM_A   0
#define FSM_B   49152
#define FSM_BAR 180224
#define FUSED_SMEM 180352

__global__ __launch_bounds__(320, 1) void fused_gemm_kernel(
    const float* __restrict__ x, float* __restrict__ out)
{
    extern __shared__ __align__(128) char smem[];
    const uint32_t sbase = smem_u32(smem);
    const int tid = threadIdx.x;
    const int m0 = blockIdx.x * 128;
    const int nimg = m0 >> 12;
    const int y0 = (m0 & 4095) >> 6;

    const uint32_t barb = sbase + FSM_BAR;   // fullA[i]=barb+8i, emptyA[i]=barb+24+8i

    if (tid == 0) {
#pragma unroll
        for (int i = 0; i < 3; i++) {
            MBAR_INIT(barb + i * 8, 64u);        // fullA
            MBAR_INIT(barb + 24 + i * 8, 256u);  // emptyA
        }
    }
    __syncthreads();

    const float* xn = x + (size_t)nimg * CC * 4096;

    if (tid < 256) {
        // ================= CONSUMERS =================
        const int ldrow = tid >> 3;
        const int ldcol = tid & 7;
        const int swzb  = ldcol ^ (ldrow & 7);
        const char* gB0 = (const char*)(g_wB + (size_t)ldrow * KDIM) + ldcol * 16;
        const uint32_t dB0 = sbase + FSM_B + ldrow * 128 + swzb * 16;

#define LOAD_B(tt_) do {                                                      \
    uint32_t so_ = ((tt_) & 3) * 32768;                                       \
    size_t   ko_ = (size_t)(tt_) * 128;                                       \
    _Pragma("unroll")                                                         \
    for (int i_ = 0; i_ < 8; i_++)                                            \
        cp_async16(dB0 + so_ + i_ * 4096,                                     \
                   gB0 + ko_ + (size_t)i_ * 32 * KDIM * 4);                   \
} while (0)

        LOAD_B(0); asm volatile("cp.async.commit_group;" ::: "memory");
        LOAD_B(1); asm volatile("cp.async.commit_group;" ::: "memory");
        LOAD_B(2); asm volatile("cp.async.commit_group;" ::: "memory");

        const int lane = tid & 31, warp = tid >> 5;
        const int g  = lane >> 2, tg = lane & 3;
        const int wm = (warp >> 2) * 64;
        const int wn = (warp & 3) * 64;

        float c[4][8][4];
#pragma unroll
        for (int i = 0; i < 4; i++)
#pragma unroll
            for (int j = 0; j < 8; j++)
#pragma unroll
                for (int r = 0; r < 4; r++) c[i][j][r] = 0.f;

        int fs = 0, fp = 0;     // fullA cursor
        int es = 0;             // emptyA arrive ring

#pragma unroll 1
        for (int t = 0; t < NTILES; t++) {
            asm volatile("bar.sync 1, 256;" ::: "memory");
            if (t >= 1) {
                MBAR_ARRIVE(barb + 24 + es * 8);
                if (++es == 3) es = 0;
            }
            if (t + 3 < NTILES) LOAD_B(t + 3);
            asm volatile("cp.async.commit_group;" ::: "memory");

            MBAR_WAIT(barb + fs * 8, fp);
            const uint32_t As = sbase + FSM_A + fs * 16384;
            if (++fs == 3) { fs = 0; fp ^= 1; }

            asm volatile("cp.async.wait_group 3;" ::: "memory");
            asm volatile("bar.sync 1, 256;" ::: "memory");

            const uint32_t Bs = sbase + FSM_B + (t & 3) * 32768;

#pragma unroll
            for (int ks = 0; ks < 4; ks++) {
                const int ch = ks * 2 + (tg >> 1);
                const int hb = (tg & 1) << 3;

                uint32_t a[4][4];
#pragma unroll
                for (int mt = 0; mt < 4; mt++) {
                    int r1 = wm + mt * 16 + g;
                    int r2 = r1 + 8;
                    uint32_t ad1 = As + r1 * 128 + ((ch ^ (r1 & 7)) << 4) + hb;
                    uint32_t ad2 = As + r2 * 128 + ((ch ^ (r2 & 7)) << 4) + hb;
                    asm volatile("ld.shared.v2.b32 {%0,%1}, [%2];"
                                 : "=r"(a[mt][0]), "=r"(a[mt][2]) : "r"(ad1));
                    asm volatile("ld.shared.v2.b32 {%0,%1}, [%2];"
                                 : "=r"(a[mt][1]), "=r"(a[mt][3]) : "r"(ad2));
                }
#pragma unroll
                for (int nt = 0; nt < 8; nt++) {
                    int rr = wn + nt * 8 + g;
                    uint32_t bd = Bs + rr * 128 + ((ch ^ (rr & 7)) << 4) + hb;
                    uint32_t b[2];
                    asm volatile("ld.shared.v2.b32 {%0,%1}, [%2];"
                                 : "=r"(b[0]), "=r"(b[1]) : "r"(bd));
#pragma unroll
                    for (int mt = 0; mt < 4; mt++)
                        MMA_TF32(c[mt][nt], a[mt], b);
                }
            }
        }

        float* ob = out + (size_t)nimg * OC * 4096 + (m0 & 4095);
#pragma unroll
        for (int mt = 0; mt < 4; mt++) {
            int lm = wm + mt * 16 + g;
#pragma unroll
            for (int nt = 0; nt < 8; nt++) {
                int o = wn + nt * 8 + tg * 2;
                ob[(size_t)o * 4096 + lm]           = c[mt][nt][0];
                ob[(size_t)(o + 1) * 4096 + lm]     = c[mt][nt][1];
                ob[(size_t)o * 4096 + lm + 8]       = c[mt][nt][2];
                ob[(size_t)(o + 1) * 4096 + lm + 8] = c[mt][nt][3];
            }
        }
    } else {
        // ================= PRODUCERS (2 warps, 64 threads) =================
        const int ptid = tid - 256;          // 0..63; owns rows ptid, ptid+64
        int   ro[2][4];
        float rw[2][4];
        int ps = 0, pp = 1;                  // emptyA cursor, phase starts 1

#pragma unroll 1
        for (int t = 0; t < NTILES; t++) {
            if ((t & 7) == 0) {
                int kk = t >> 3;
#pragma unroll
                for (int rr = 0; rr < 2; rr++) {
                    int row = ptid + rr * 64;
                    int yy = y0 + (row >> 6);
                    int xx = row & 63;
                    const float* omn = g_om + (size_t)nimg * 27 * 4096 + yy * 64 + xx;
                    float oy = omn[(size_t)(2 * kk) * 4096];
                    float ox = omn[(size_t)(2 * kk + 1) * 4096];
                    float mv = omn[(size_t)(18 + kk) * 4096];
                    float m  = 1.f / (1.f + __expf(-mv));

                    float py = (float)(yy + kk / 3) + oy;
                    float px = (float)(xx + (kk % 3)) + ox;
                    py = fminf(fmaxf(py, 0.f), 65.f);
                    px = fminf(fmaxf(px, 0.f), 65.f);
                    float fy = floorf(py), fx = floorf(px);
                    int y1 = (int)fy, x1 = (int)fx;
                    float ly = py - fy, lx = px - fx;
                    float hy = 1.f - ly, hx = 1.f - lx;
                    float wq[4] = { hy * hx, hy * lx, ly * hx, ly * lx };
#pragma unroll
                    for (int q = 0; q < 4; q++) {
                        int Y = y1 + (q >> 1);
                        int X = x1 + (q & 1);
                        bool vld = (Y >= 1 && Y <= 64 && X >= 1 && X <= 64);
                        int Yc = min(max(Y, 1), 64), Xc = min(max(X, 1), 64);
                        ro[rr][q] = (Yc - 1) * 64 + (Xc - 1);
                        rw[rr][q] = vld ? wq[q] * m : 0.f;
                    }
                }
            }

            MBAR_WAIT(barb + 24 + ps * 8, pp);   // wait emptyA[ps]
            const uint32_t Abase = sbase + FSM_A + ps * 16384;
            const int c0 = (t & 7) * 32;
            const float* xp = xn + (size_t)c0 * 4096;

#pragma unroll
            for (int rr = 0; rr < 2; rr++) {
                const int row = ptid + rr * 64;
                const uint32_t Aw = Abase + row * 128;
                const int swl = (row & 7);
#pragma unroll
                for (int g8 = 0; g8 < 4; g8++) {
#pragma unroll
                    for (int q = 0; q < 4; q++) {
                        int ct = g8 * 8 + q;
                        const float* plo = xp + (size_t)ct * 4096;
                        const float* phi = plo + 4 * 4096;
                        float vlo = rw[rr][0] * __ldg(&plo[ro[rr][0]])
                                  + rw[rr][1] * __ldg(&plo[ro[rr][1]])
                                  + rw[rr][2] * __ldg(&plo[ro[rr][2]])
                                  + rw[rr][3] * __ldg(&plo[ro[rr][3]]);
                        float vhi = rw[rr][0] * __ldg(&phi[ro[rr][0]])
                                  + rw[rr][1] * __ldg(&phi[ro[rr][1]])
                                  + rw[rr][2] * __ldg(&phi[ro[rr][2]])
                                  + rw[rr][3] * __ldg(&phi[ro[rr][3]]);
                        int cp = g8 * 8 + (q << 1);
                        uint32_t addr = Aw + ((((uint32_t)cp >> 2) ^ swl) << 4)
                                      + ((cp & 3) << 2);
                        asm volatile("st.shared.v2.b32 [%0], {%1,%2};"
                                     :: "r"(addr),
                                        "r"(__float_as_uint(to_tf32(vlo))),
                                        "r"(__float_as_uint(to_tf32(vhi))) : "memory");
                    }
                }
            }

            MBAR_ARRIVE(barb + ps * 8);          // fullA[ps] (release)
            if (++ps == 3) { ps = 0; pp ^= 1; }
        }
    }
}

// ---------------------------------------------------------------------------
extern "C" void kernel_launch(void* const* d_in, const int* in_sizes, int n_in,
                              void* d_out, int out_size)
{
    const float* x      = (const float*)d_in[0];
    const float* conv_w = (const float*)d_in[1];
    const float* conv_b = (const float*)d_in[2];
    const float* dcn_w  = (const float*)d_in[3];
    float* out = (float*)d_out;

    cudaFuncSetAttribute(offset_gemm_kernel,
                         cudaFuncAttributeMaxDynamicSharedMemorySize, OFF_SMEM);
    cudaFuncSetAttribute(fused_gemm_kernel,
                         cudaFuncAttributeMaxDynamicSharedMemorySize, FUSED_SMEM);

    permute_w_kernel<<<OC, 256>>>(dcn_w);
    permute_woff_kernel<<<32, 256>>>(conv_w);
    offset_gemm_kernel<<<MDIM / 128, 256, OFF_SMEM>>>(x, conv_b);
    fused_gemm_kernel<<<MDIM / 128, 320, FUSED_SMEM>>>(x, out);
}

// round 10
// speedup vs baseline: 1.1542x; 1.1542x over previous
#include <cuda_runtime.h>
#include <cuda_bf16.h>
#include <math.h>
#include <cstdint>

// Shapes (fixed)
//   x: (4,256,64,64) f32 | conv_offset_w: (27,256,3,3) | conv_offset_b: (27,)
//   dcn_weight: (256,256,3,3) | out: (4,256,64,64) f32
//
// Pipeline (all tensor-core):
//   K2a permute dcn_weight    -> g_wB[o][k']      tf32, k 8-group permuted
//   K2b permute conv_offset_w -> g_wOffHi/Lo[32][k'] split-tf32
//   K3  offset implicit GEMM  -> g_om  (split-tf32, reg-prefetched gather)
//   K4  FUSED sample+GEMM, homogeneous 512 threads (16 warps, warp tile 32x64)

#define NN 4
#define CC 256
#define HH 64
#define WW 64
#define OC 256
#define KDIM 2304
#define MDIM 16384
#define NTILES 72

__device__ __align__(128) float g_om[NN * 27 * HH * WW];
__device__ __align__(128) float g_wB[OC * KDIM];
__device__ __align__(128) float g_wOffHi[32 * KDIM];
__device__ __align__(128) float g_wOffLo[32 * KDIM];

__device__ __forceinline__ float to_tf32(float v) {
    uint32_t u;
    asm("cvt.rna.tf32.f32 %0, %1;" : "=r"(u) : "f"(v));
    return __uint_as_float(u);
}
__device__ __forceinline__ uint32_t smem_u32(const void* p) {
    uint32_t a;
    asm("{ .reg .u64 t; cvta.to.shared.u64 t, %1; cvt.u32.u64 %0, t; }"
        : "=r"(a) : "l"(p));
    return a;
}
__device__ __forceinline__ void cp_async16(uint32_t d, const void* s) {
    asm volatile("cp.async.cg.shared.global [%0], [%1], 16;"
                 :: "r"(d), "l"(s) : "memory");
}

#define MMA_TF32(c_, a_, b_)                                                  \
    asm volatile(                                                             \
        "mma.sync.aligned.m16n8k8.row.col.f32.tf32.tf32.f32 "                 \
        "{%0,%1,%2,%3}, {%4,%5,%6,%7}, {%8,%9}, {%0,%1,%2,%3};"               \
        : "+f"((c_)[0]), "+f"((c_)[1]), "+f"((c_)[2]), "+f"((c_)[3])          \
        : "r"((a_)[0]), "r"((a_)[1]), "r"((a_)[2]), "r"((a_)[3]),             \
          "r"((b_)[0]), "r"((b_)[1]))

// ---------------------------------------------------------------------------
// K2a: permute dcn_weight (o,c,kk) -> g_wB[o][k'], tf32-rounded, k-permuted
// ---------------------------------------------------------------------------
__global__ __launch_bounds__(256) void permute_w_kernel(const float* __restrict__ dw)
{
    int o = blockIdx.x;
    int c = threadIdx.x;
    int cp = (c & 0xF8) | ((c & 3) << 1) | ((c >> 2) & 1);
    const float* src = dw + (size_t)(o * CC + c) * 9;
    float* dst = g_wB + (size_t)o * KDIM + cp;
#pragma unroll
    for (int kk = 0; kk < 9; kk++)
        dst[kk * 256] = to_tf32(src[kk]);
}

// ---------------------------------------------------------------------------
// K2b: permute conv_offset_w -> g_wOffHi/Lo[32][k'] (split-tf32)
// ---------------------------------------------------------------------------
__global__ __launch_bounds__(256) void permute_woff_kernel(const float* __restrict__ wo)
{
    int o = blockIdx.x;
    int c = threadIdx.x;
    int cp = (c & 0xF8) | ((c & 3) << 1) | ((c >> 2) & 1);
    float* dh = g_wOffHi + (size_t)o * KDIM + cp;
    float* dl = g_wOffLo + (size_t)o * KDIM + cp;
    if (o < 27) {
        const float* src = wo + (size_t)(o * CC + c) * 9;
#pragma unroll
        for (int kk = 0; kk < 9; kk++) {
            float v = src[kk];
            float h = to_tf32(v);
            dh[kk * 256] = h;
            dl[kk * 256] = to_tf32(v - h);
        }
    } else {
#pragma unroll
        for (int kk = 0; kk < 9; kk++) { dh[kk * 256] = 0.f; dl[kk * 256] = 0.f; }
    }
}

// ---------------------------------------------------------------------------
// K3: offset conv as split-tf32 implicit GEMM, register-prefetched gather.
// BM=128, BN=32, BK=32.  smem: A 2buf x 32KB @0 | B 4 stages x 8KB @65536
// (unchanged from R9 — measured fine)
// ---------------------------------------------------------------------------
#define OSM_A 0
#define OSM_B 65536
#define OFF_SMEM 98304

__global__ __launch_bounds__(256, 1) void offset_gemm_kernel(
    const float* __restrict__ x, const float* __restrict__ bias)
{
    extern __shared__ __align__(128) char smem[];
    const uint32_t sbase = smem_u32(smem);
    const int tid = threadIdx.x;
    const int m0 = blockIdx.x * 128;
    const int nimg = m0 >> 12;
    const int y0 = (m0 & 4095) >> 6;

    const int ldrow = tid >> 3;
    const int ldcol = tid & 7;
    const int swzb  = ldcol ^ (ldrow & 7);
    const char* gBh = (const char*)(g_wOffHi + (size_t)ldrow * KDIM) + ldcol * 16;
    const char* gBl = (const char*)(g_wOffLo + (size_t)ldrow * KDIM) + ldcol * 16;
    const uint32_t dBh = sbase + OSM_B + ldrow * 128 + swzb * 16;

#define LOAD_OB(tt_) do {                                                     \
    uint32_t so_ = ((tt_) & 3) * 8192;                                        \
    size_t   ko_ = (size_t)(tt_) * 128;                                       \
    cp_async16(dBh + so_, gBh + ko_);                                         \
    cp_async16(dBh + so_ + 4096, gBl + ko_);                                  \
} while (0)

    LOAD_OB(0); asm volatile("cp.async.commit_group;" ::: "memory");
    LOAD_OB(1); asm volatile("cp.async.commit_group;" ::: "memory");
    LOAD_OB(2); asm volatile("cp.async.commit_group;" ::: "memory");

    const int mloc = tid & 127;
    const int half = tid >> 7;
    const int lane = tid & 31, warp = tid >> 5;
    const int g  = lane >> 2, tg = lane & 3;
    const int wm = warp * 16;

    const float* xn = x + (size_t)nimg * CC * 4096;

    float c[4][4];
#pragma unroll
    for (int i = 0; i < 4; i++)
#pragma unroll
        for (int r = 0; r < 4; r++) c[i][r] = 0.f;

    int soff = 0;
    bool valid = false;
    float R0[16], R1[16];

    auto gather16 = [&](float* R, int tt) {
        if ((tt & 7) == 0) {
            int kk = tt >> 3;
            int yy = y0 + (mloc >> 6) + kk / 3 - 1;
            int xx = (mloc & 63) + kk % 3 - 1;
            valid = ((unsigned)yy < 64u) && ((unsigned)xx < 64u);
            soff = yy * 64 + xx;
        }
        const float* xp = xn + (size_t)((tt & 7) * 32) * 4096;
#pragma unroll
        for (int i = 0; i < 8; i++) {
            int ct = half * 16 + (i >> 2) * 8 + (i & 3);
            R[i * 2]     = valid ? __ldg(xp + (size_t)ct * 4096 + soff) : 0.f;
            R[i * 2 + 1] = valid ? __ldg(xp + (size_t)(ct + 4) * 4096 + soff) : 0.f;
        }
    };
    auto sts16 = [&](const float* R, int tt) {
        const uint32_t Awh = sbase + OSM_A + (tt & 1) * 32768 + mloc * 128;
#pragma unroll
        for (int i = 0; i < 8; i++) {
            int q = i & 3;
            int ct = half * 16 + (i >> 2) * 8 + q;
            float v0 = R[i * 2], v1 = R[i * 2 + 1];
            float h0 = to_tf32(v0), l0 = to_tf32(v0 - h0);
            float h1 = to_tf32(v1), l1 = to_tf32(v1 - h1);
            int cp = (ct & 0x18) | (q << 1);
            uint32_t off = ((((uint32_t)cp >> 2) ^ (mloc & 7)) << 4) + ((cp & 3) << 2);
            asm volatile("st.shared.v2.b32 [%0], {%1,%2};"
                         :: "r"(Awh + off),
                            "r"(__float_as_uint(h0)), "r"(__float_as_uint(h1)) : "memory");
            asm volatile("st.shared.v2.b32 [%0], {%1,%2};"
                         :: "r"(Awh + 16384 + off),
                            "r"(__float_as_uint(l0)), "r"(__float_as_uint(l1)) : "memory");
        }
    };
    auto mma_tile = [&](int tt) {
        const uint32_t As = sbase + OSM_A + (tt & 1) * 32768;
        const uint32_t Bs = sbase + OSM_B + (tt & 3) * 8192;
#pragma unroll
        for (int ks = 0; ks < 4; ks++) {
            const int ch = ks * 2 + (tg >> 1);
            const int hb = (tg & 1) << 3;
            uint32_t ah[4], al[4];
            {
                int r1 = wm + g, r2 = r1 + 8;
                uint32_t ad1 = As + r1 * 128 + ((ch ^ (r1 & 7)) << 4) + hb;
                uint32_t ad2 = As + r2 * 128 + ((ch ^ (r2 & 7)) << 4) + hb;
                asm volatile("ld.shared.v2.b32 {%0,%1}, [%2];"
                             : "=r"(ah[0]), "=r"(ah[2]) : "r"(ad1));
                asm volatile("ld.shared.v2.b32 {%0,%1}, [%2];"
                             : "=r"(ah[1]), "=r"(ah[3]) : "r"(ad2));
                asm volatile("ld.shared.v2.b32 {%0,%1}, [%2];"
                             : "=r"(al[0]), "=r"(al[2]) : "r"(ad1 + 16384));
                asm volatile("ld.shared.v2.b32 {%0,%1}, [%2];"
                             : "=r"(al[1]), "=r"(al[3]) : "r"(ad2 + 16384));
            }
#pragma unroll
            for (int nt = 0; nt < 4; nt++) {
                int rr = nt * 8 + g;
                uint32_t bd = Bs + rr * 128 + ((ch ^ (rr & 7)) << 4) + hb;
                uint32_t bh[2], bl[2];
                asm volatile("ld.shared.v2.b32 {%0,%1}, [%2];"
                             : "=r"(bh[0]), "=r"(bh[1]) : "r"(bd));
                asm volatile("ld.shared.v2.b32 {%0,%1}, [%2];"
                             : "=r"(bl[0]), "=r"(bl[1]) : "r"(bd + 4096));
                MMA_TF32(c[nt], ah, bh);
                MMA_TF32(c[nt], ah, bl);
                MMA_TF32(c[nt], al, bh);
            }
        }
    };

    gather16(R0, 0);

#pragma unroll 1
    for (int t = 0; t < NTILES; t += 2) {
        sts16(R0, t);
        gather16(R1, t + 1);
        asm volatile("cp.async.wait_group 2;" ::: "memory");
        __syncthreads();
        if (t + 3 < NTILES) LOAD_OB(t + 3);
        asm volatile("cp.async.commit_group;" ::: "memory");
        mma_tile(t);

        sts16(R1, t + 1);
        if (t + 2 < NTILES) gather16(R0, t + 2);
        asm volatile("cp.async.wait_group 2;" ::: "memory");
        __syncthreads();
        if (t + 4 < NTILES) LOAD_OB(t + 4);
        asm volatile("cp.async.commit_group;" ::: "memory");
        mma_tile(t + 1);
    }

    float* ob = g_om + (size_t)nimg * 27 * 4096 + (m0 & 4095);
    int lm = wm + g;
#pragma unroll
    for (int nt = 0; nt < 4; nt++) {
        int oc0 = nt * 8 + tg * 2;
        if (oc0 < 27) {
            float bb = bias[oc0];
            ob[(size_t)oc0 * 4096 + lm]     = c[nt][0] + bb;
            ob[(size_t)oc0 * 4096 + lm + 8] = c[nt][2] + bb;
        }
        if (oc0 + 1 < 27) {
            float bb = bias[oc0 + 1];
            ob[(size_t)(oc0 + 1) * 4096 + lm]     = c[nt][1] + bb;
            ob[(size_t)(oc0 + 1) * 4096 + lm + 8] = c[nt][3] + bb;
        }
    }
}

// ---------------------------------------------------------------------------
// K4: FUSED sample+GEMM, 512 threads (16 warps, 4 per SMSP).
// BM=128, BN=256, BK=32. Warp tile 32x64 (mt 0..1, nt 0..7).
// smem: A dbl-buf 2x16KB @0 | B 4-stage 4x32KB @32768 | metadata @163840
// ---------------------------------------------------------------------------
#define SM_A    0
#define SM_B    32768
#define SM_MOFF 163840
#define SM_MWT  182272
#define FUSED_SMEM 200704

__global__ __launch_bounds__(512, 1) void fused_gemm_kernel(
    const float* __restrict__ x, float* __restrict__ out)
{
    extern __shared__ __align__(128) char smem[];
    const uint32_t sbase = smem_u32(smem);
    const int tid = threadIdx.x;
    const int m0 = blockIdx.x * 128;
    const int nimg = m0 >> 12;
    const int y0 = (m0 & 4095) >> 6;

    int4*   moff = (int4*)(smem + SM_MOFF);
    float4* mwt  = (float4*)(smem + SM_MWT);

    // ---- B cp.async: 2048 16B-chunks/stage, 4 per thread (rows +0,64,128,192)
    const int ldrow = tid >> 3;          // 0..63
    const int ldcol = tid & 7;
    const int swzb  = ldcol ^ (ldrow & 7);
    const char* gB0 = (const char*)(g_wB + (size_t)ldrow * KDIM) + ldcol * 16;
    const uint32_t dB0 = sbase + SM_B + ldrow * 128 + swzb * 16;

#define LOAD_B(tt_) do {                                                      \
    uint32_t so_ = ((tt_) & 3) * 32768;                                       \
    size_t   ko_ = (size_t)(tt_) * 128;                                       \
    _Pragma("unroll")                                                         \
    for (int i_ = 0; i_ < 4; i_++)                                            \
        cp_async16(dB0 + so_ + i_ * 8192,                                     \
                   gB0 + ko_ + (size_t)i_ * 64 * KDIM * 4);                   \
} while (0)

    LOAD_B(0); asm volatile("cp.async.commit_group;" ::: "memory");
    LOAD_B(1); asm volatile("cp.async.commit_group;" ::: "memory");
    LOAD_B(2); asm volatile("cp.async.commit_group;" ::: "memory");

    // ---- metadata: per (pixel, kk) tap offsets + folded weights ----
    for (int idx = tid; idx < 1152; idx += 512) {
        int p128 = idx / 9, kk = idx - p128 * 9;
        int yy = y0 + (p128 >> 6);
        int xx = p128 & 63;
        const float* omn = g_om + (size_t)nimg * 27 * 4096 + yy * 64 + xx;
        float oy = omn[(size_t)(2 * kk) * 4096];
        float ox = omn[(size_t)(2 * kk + 1) * 4096];
        float mv = omn[(size_t)(18 + kk) * 4096];
        float m  = 1.f / (1.f + __expf(-mv));

        float py = (float)(yy + kk / 3) + oy;
        float px = (float)(xx + (kk % 3)) + ox;
        py = fminf(fmaxf(py, 0.f), 65.f);
        px = fminf(fmaxf(px, 0.f), 65.f);
        float fy = floorf(py), fx = floorf(px);
        int y1 = (int)fy, x1 = (int)fx;
        float ly = py - fy, lx = px - fx;
        float hy = 1.f - ly, hx = 1.f - lx;
        float wq[4] = { hy * hx, hy * lx, ly * hx, ly * lx };

        int4 o4; float4 w4;
        int   ov[4]; float wv[4];
#pragma unroll
        for (int q = 0; q < 4; q++) {
            int Y = y1 + (q >> 1);
            int X = x1 + (q & 1);
            bool valid = (Y >= 1 && Y <= 64 && X >= 1 && X <= 64);
            int Yc = min(max(Y, 1), 64), Xc = min(max(X, 1), 64);
            ov[q] = (Yc - 1) * 64 + (Xc - 1);
            wv[q] = valid ? wq[q] * m : 0.f;
        }
        o4.x = ov[0]; o4.y = ov[1]; o4.z = ov[2]; o4.w = ov[3];
        w4.x = wv[0]; w4.y = wv[1]; w4.z = wv[2]; w4.w = wv[3];
        moff[idx] = o4;
        mwt[idx]  = w4;
    }
    __syncthreads();

    // ---- roles ----
    const int mloc = tid & 127;              // gather pixel row
    const int quad = tid >> 7;               // 0..3 -> channels quad*8 .. +7
    const int lane = tid & 31, warp = tid >> 5;
    const int g  = lane >> 2, tg = lane & 3;
    const int wm = (warp >> 2) * 32;         // 4 warp-rows x 32
    const int wn = (warp & 3) * 64;          // 4 warp-cols x 64

    const float* xn = x + (size_t)nimg * CC * 4096;

    float c[2][8][4];
#pragma unroll
    for (int i = 0; i < 2; i++)
#pragma unroll
        for (int j = 0; j < 8; j++)
#pragma unroll
            for (int r = 0; r < 4; r++) c[i][j][r] = 0.f;

    int   ro[4];
    float rw[4];

#pragma unroll 1
    for (int t = 0; t < NTILES; t++) {
        if ((t & 7) == 0) {
            int kk = t >> 3;
            int4   o4 = moff[mloc * 9 + kk];
            float4 w4 = mwt [mloc * 9 + kk];
            ro[0] = o4.x; ro[1] = o4.y; ro[2] = o4.z; ro[3] = o4.w;
            rw[0] = w4.x; rw[1] = w4.y; rw[2] = w4.z; rw[3] = w4.w;
        }

        // ---- gather A(t): 8 values/thread (4 x st.v2) ----
        {
            const int c0 = (t & 7) * 32;
            const float* xp = xn + (size_t)c0 * 4096;
            const uint32_t Aw = sbase + SM_A + (t & 1) * 16384 + mloc * 128;
#pragma unroll
            for (int q = 0; q < 4; q++) {
                int ct = quad * 8 + q;
                const float* plo = xp + (size_t)ct * 4096;
                const float* phi = plo + 4 * 4096;
                float vlo = rw[0] * __ldg(&plo[ro[0]])
                          + rw[1] * __ldg(&plo[ro[1]])
                          + rw[2] * __ldg(&plo[ro[2]])
                          + rw[3] * __ldg(&plo[ro[3]]);
                float vhi = rw[0] * __ldg(&phi[ro[0]])
                          + rw[1] * __ldg(&phi[ro[1]])
                          + rw[2] * __ldg(&phi[ro[2]])
                          + rw[3] * __ldg(&phi[ro[3]]);
                int cp = quad * 8 + (q << 1);
                uint32_t addr = Aw + ((((uint32_t)cp >> 2) ^ (mloc & 7)) << 4)
                              + ((cp & 3) << 2);
                asm volatile("st.shared.v2.b32 [%0], {%1,%2};"
                             :: "r"(addr),
                                "r"(__float_as_uint(to_tf32(vlo))),
                                "r"(__float_as_uint(to_tf32(vhi))) : "memory");
            }
        }

        asm volatile("cp.async.wait_group 2;" ::: "memory");
        __syncthreads();   // A(t) STS drained + B(t) resident

        if (t + 3 < NTILES) LOAD_B(t + 3);
        asm volatile("cp.async.commit_group;" ::: "memory");

        const uint32_t As = sbase + SM_A + (t & 1) * 16384;
        const uint32_t Bs = sbase + SM_B + (t & 3) * 32768;

#pragma unroll
        for (int ks = 0; ks < 4; ks++) {
            const int ch = ks * 2 + (tg >> 1);
            const int hb = (tg & 1) << 3;

            uint32_t a[2][4];
#pragma unroll
            for (int mt = 0; mt < 2; mt++) {
                int r1 = wm + mt * 16 + g;
                int r2 = r1 + 8;
                uint32_t ad1 = As + r1 * 128 + ((ch ^ (r1 & 7)) << 4) + hb;
                uint32_t ad2 = As + r2 * 128 + ((ch ^ (r2 & 7)) << 4) + hb;
                asm volatile("ld.shared.v2.b32 {%0,%1}, [%2];"
                             : "=r"(a[mt][0]), "=r"(a[mt][2]) : "r"(ad1));
                asm volatile("ld.shared.v2.b32 {%0,%1}, [%2];"
                             : "=r"(a[mt][1]), "=r"(a[mt][3]) : "r"(ad2));
            }
#pragma unroll
            for (int nt = 0; nt < 8; nt++) {
                int rr = wn + nt * 8 + g;
                uint32_t bd = Bs + rr * 128 + ((ch ^ (rr & 7)) << 4) + hb;
                uint32_t b[2];
                asm volatile("ld.shared.v2.b32 {%0,%1}, [%2];"
                             : "=r"(b[0]), "=r"(b[1]) : "r"(bd));
                MMA_TF32(c[0][nt], a[0], b);
                MMA_TF32(c[1][nt], a[1], b);
            }
        }
    }

    // ---- epilogue ----
    float* ob = out + (size_t)nimg * OC * 4096 + (m0 & 4095);
#pragma unroll
    for (int mt = 0; mt < 2; mt++) {
        int lm = wm + mt * 16 + g;
#pragma unroll
        for (int nt = 0; nt < 8; nt++) {
            int o = wn + nt * 8 + tg * 2;
            ob[(size_t)o * 4096 + lm]           = c[mt][nt][0];
            ob[(size_t)(o + 1) * 4096 + lm]     = c[mt][nt][1];
            ob[(size_t)o * 4096 + lm + 8]       = c[mt][nt][2];
            ob[(size_t)(o + 1) * 4096 + lm + 8] = c[mt][nt][3];
        }
    }
}

// ---------------------------------------------------------------------------
extern "C" void kernel_launch(void* const* d_in, const int* in_sizes, int n_in,
                              void* d_out, int out_size)
{
    const float* x      = (const float*)d_in[0];
    const float* conv_w = (const float*)d_in[1];
    const float* conv_b = (const float*)d_in[2];
    const float* dcn_w  = (const float*)d_in[3];
    float* out = (float*)d_out;

    cudaFuncSetAttribute(offset_gemm_kernel,
                         cudaFuncAttributeMaxDynamicSharedMemorySize, OFF_SMEM);
    cudaFuncSetAttribute(fused_gemm_kernel,
                         cudaFuncAttributeMaxDynamicSharedMemorySize, FUSED_SMEM);

    permute_w_kernel<<<OC, 256>>>(dcn_w);
    permute_woff_kernel<<<32, 256>>>(conv_w);
    offset_gemm_kernel<<<MDIM / 128, 256, OFF_SMEM>>>(x, conv_b);
    fused_gemm_kernel<<<MDIM / 128, 512, FUSED_SMEM>>>(x, out);
}